// round 15
// baseline (speedup 1.0000x reference)
#include <cuda_runtime.h>
#include <stdint.h>
#include <math.h>

#define N_TOK 16384
#define D_DIM 256
#define H_DIM 1024
#define N_EXP 8
#define MT    32
// Max FFN work tiles: sum_e ceil(cnt_e/MT) <= (2*N_TOK)/MT + N_EXP = 1032
#define MAX_TILES (2 * N_TOK / MT + N_EXP)

// ---------------- device-global scratch (static: allowed) ----------------
__device__ int   g_count[N_EXP];
__device__ float g_probsum[N_EXP];
__device__ int   g_tok[N_EXP * N_TOK];
__device__ float g_p  [N_EXP * N_TOK];

// ---------------- cp.async helpers ----------------
#define CP_ASYNC16(dst_u32, src_ptr) \
    asm volatile("cp.async.cg.shared.global [%0], [%1], 16;\n" :: "r"(dst_u32), "l"(src_ptr))
#define CP_COMMIT() asm volatile("cp.async.commit_group;\n" ::: "memory")
#define CP_WAIT0()  asm volatile("cp.async.wait_group 0;\n"  ::: "memory")

// packed f32x2 FMA (SASS FFMA2) — ptxas never emits this from C++; PTX-only.
#define FMA_F32X2(acc, a, b) \
    asm("fma.rn.f32x2 %0, %1, %2, %0;" : "+l"(acc) : "l"(a), "l"(b))

// ---------------- init: zero out + counters ----------------
__global__ void init_kernel(float* __restrict__ out) {
    int i = blockIdx.x * blockDim.x + threadIdx.x;   // 4096*256 = (N*D)/4
    ((float4*)out)[i] = make_float4(0.f, 0.f, 0.f, 0.f);
    if (blockIdx.x == 0 && threadIdx.x < N_EXP) {
        g_count[threadIdx.x]   = 0;
        g_probsum[threadIdx.x] = 0.f;
    }
}

// ---------------- router: logits, softmax, top-2, scatter ----------------
__global__ void router_kernel(const float* __restrict__ x,
                              const float* __restrict__ rw,
                              const float* __restrict__ tg) {
    __shared__ float s_rw[3 * D_DIM];
    __shared__ float s_tg[N_EXP * 3];
    __shared__ float s_ps[N_EXP];
    int tid = threadIdx.x;
    for (int i = tid; i < 3 * D_DIM; i += 256) s_rw[i] = rw[i];
    if (tid < N_EXP * 3) s_tg[tid] = tg[tid];
    if (tid < N_EXP)     s_ps[tid] = 0.f;
    __syncthreads();

    int tok = blockIdx.x * 256 + tid;
    const float4* xr = (const float4*)(x + (size_t)tok * D_DIM);
    float z0 = 0.f, z1 = 0.f, z2 = 0.f;
    #pragma unroll 8
    for (int k4 = 0; k4 < 64; ++k4) {
        float4 v = xr[k4];
        int k = k4 * 4;
        z0 = fmaf(v.x, s_rw[k + 0], z0); z0 = fmaf(v.y, s_rw[k + 1], z0);
        z0 = fmaf(v.z, s_rw[k + 2], z0); z0 = fmaf(v.w, s_rw[k + 3], z0);
        z1 = fmaf(v.x, s_rw[256 + k + 0], z1); z1 = fmaf(v.y, s_rw[256 + k + 1], z1);
        z1 = fmaf(v.z, s_rw[256 + k + 2], z1); z1 = fmaf(v.w, s_rw[256 + k + 3], z1);
        z2 = fmaf(v.x, s_rw[512 + k + 0], z2); z2 = fmaf(v.y, s_rw[512 + k + 1], z2);
        z2 = fmaf(v.z, s_rw[512 + k + 2], z2); z2 = fmaf(v.w, s_rw[512 + k + 3], z2);
    }

    float p[N_EXP];
    float m = -1e30f;
    #pragma unroll
    for (int e = 0; e < N_EXP; ++e) {
        float l = z0 * s_tg[e * 3 + 0] + z1 * s_tg[e * 3 + 1] + z2 * s_tg[e * 3 + 2];
        p[e] = l;
        m = fmaxf(m, l);
    }
    float sum = 0.f;
    #pragma unroll
    for (int e = 0; e < N_EXP; ++e) { p[e] = expf(p[e] - m); sum += p[e]; }
    float inv = 1.f / sum;
    #pragma unroll
    for (int e = 0; e < N_EXP; ++e) p[e] *= inv;

    #pragma unroll
    for (int e = 0; e < N_EXP; ++e) atomicAdd(&s_ps[e], p[e]);

    // top-2 with first-index tiebreak (matches jax.lax.top_k)
    int i0 = 0;
    #pragma unroll
    for (int e = 1; e < N_EXP; ++e) if (p[e] > p[i0]) i0 = e;
    int i1 = -1;
    #pragma unroll
    for (int e = 0; e < N_EXP; ++e) {
        if (e == i0) continue;
        if (i1 < 0 || p[e] > p[i1]) i1 = e;
    }
    float pn = p[i0] + p[i1] + 1e-8f;
    float q0 = p[i0] / pn, q1 = p[i1] / pn;

    int s0 = atomicAdd(&g_count[i0], 1);
    g_tok[i0 * N_TOK + s0] = tok;  g_p[i0 * N_TOK + s0] = q0;
    int s1 = atomicAdd(&g_count[i1], 1);
    g_tok[i1 * N_TOK + s1] = tok;  g_p[i1 * N_TOK + s1] = q1;

    __syncthreads();
    if (tid < N_EXP) atomicAdd(&g_probsum[tid], s_ps[tid]);
}

// ---------------- fused sparse FFN ----------------
__device__ __forceinline__ float gelu_exact(float v) {
    return 0.5f * v * (1.f + erff(v * 0.70710678118654752440f));
}

// smem: xs[32][256], hs[32][128], UA[256|128][64], UB  (all XOR-swizzled)
// swizzle: within each 128B group of a row, 16B-block low3 bits XOR (key);
// bit 3 of the block index passes through untouched. Reading physical block
// (kk&8)|((kk^key)&7) with the writer's key retrieves logical block kk, so
// summing over all kk covers every logical block exactly once.
#define XS_FLOATS (32 * 256)
#define HS_FLOATS (32 * 128)
#define U_FLOATS  (256 * 64)
#define SMEM_FLOATS (XS_FLOATS + HS_FLOATS + 2 * U_FLOATS)   // 45056 -> 176 KB

// Stage HALF of a W1 slab (passes half*4 .. half*4+3): 128 rows x 64 floats total
__device__ __forceinline__ void stage_w1_half(uint32_t u, const float* __restrict__ W1e,
                                              int hc, int kt, int tid, int half) {
    #pragma unroll
    for (int pp = 0; pp < 4; ++pp) {
        int q = (half * 4 + pp) * 256 + tid;
        int j = q >> 4, kk = q & 15;
        const float* src = W1e + (size_t)(hc * 128 + j) * D_DIM + kt * 64 + kk * 4;
        uint32_t dst = u + (uint32_t)(j * 64 + (((kk & 8) | ((kk ^ (j >> 2)) & 7))) * 4) * 4u;
        CP_ASYNC16(dst, src);
    }
}

// Stage HALF of a W2 slab (passes half*8 .. half*8+7): 256 rows x 64 floats total
__device__ __forceinline__ void stage_w2_half(uint32_t u, const float* __restrict__ W2e,
                                              int hc, int hk, int tid, int half) {
    #pragma unroll
    for (int pp = 0; pp < 8; ++pp) {
        int q = (half * 8 + pp) * 256 + tid;
        int d = q >> 4, hh = q & 15;
        const float* src = W2e + (size_t)d * H_DIM + hc * 128 + hk * 64 + hh * 4;
        uint32_t dst = u + (uint32_t)(d * 64 + (((hh & 8) | ((hh ^ (d >> 2)) & 7))) * 4) * 4u;
        CP_ASYNC16(dst, src);
    }
}

__global__ void __launch_bounds__(256)
ffn_kernel(const float* __restrict__ x, const float* __restrict__ W1,
           const float* __restrict__ W2, float* __restrict__ out) {
    // Dense work map: bid -> (expert e, tile) via inline prefix over tile counts.
    // Pure function of g_count, identical across blocks; total tiles <= MAX_TILES.
    int bid = blockIdx.x;
    int e = 0, tile = 0, cnt = 0;
    {
        int base = 0, found = 0;
        #pragma unroll
        for (int ee = 0; ee < N_EXP; ++ee) {
            int c  = g_count[ee];
            int nt = (c + MT - 1) / MT;
            if (!found && bid < base + nt) {
                e = ee; tile = bid - base; cnt = c; found = 1;
            }
            base += nt;
        }
        if (!found) return;            // bid beyond total tiles
    }
    int m0 = tile * MT;

    extern __shared__ float sm[];
    float* xs = sm;                          // 32*256
    float* hs = sm + XS_FLOATS;              // 32*128
    float* U0 = sm + XS_FLOATS + HS_FLOATS;  // 256*64
    float* U1 = U0 + U_FLOATS;               // 256*64
    uint32_t xsu = (uint32_t)__cvta_generic_to_shared(xs);
    uint32_t u0  = (uint32_t)__cvta_generic_to_shared(U0);
    uint32_t u1  = (uint32_t)__cvta_generic_to_shared(U1);
    __shared__ int   s_tok[MT];
    __shared__ float s_p[MT];

    int tid = threadIdx.x;

    const float* W1e = W1 + (size_t)e * H_DIM * D_DIM;
    const float* W2e = W2 + (size_t)e * D_DIM * H_DIM;

    if (tid < MT) {
        int idx = m0 + tid;
        if (idx < cnt) { s_tok[tid] = g_tok[e * N_TOK + idx]; s_p[tid] = g_p[e * N_TOK + idx]; }
        else           { s_tok[tid] = -1;                     s_p[tid] = 0.f; }
    }
    __syncthreads();

    // Fully asynchronous prologue: x-gather AND first W1 slab via cp.async in
    // one commit group. The mainloop's first CP_WAIT0 + barrier covers both.
    #pragma unroll
    for (int pass = 0; pass < 8; ++pass) {
        int q = pass * 256 + tid;
        int row = q >> 6, c4 = q & 63;
        int t = s_tok[row]; if (t < 0) t = 0;
        const float* src = x + (size_t)t * D_DIM + c4 * 4;
        int phys = (c4 & ~7) | ((c4 ^ (row >> 2)) & 7);
        CP_ASYNC16(xsu + (uint32_t)(row * 256 + phys * 4) * 4u, src);
    }
    stage_w1_half(u0, W1e, 0, 0, tid, 0);
    stage_w1_half(u0, W1e, 0, 0, tid, 1);
    CP_COMMIT();

    int tt = tid & 7;          // token group (4 rows); xs/hs swizzle key
    int th = tid >> 3;         // 0..31
    int keyW1 = th & 7;        // U(W1) read key: (j>>2)&7 with j = th*4+dd -> th&7

    // GEMM2 accumulators as packed f32x2 pairs over the reduction dim:
    // pair = (even-hh partial, odd-hh partial); folded only in the epilogue.
    unsigned long long acc2p[4][8];
    #pragma unroll
    for (int ii = 0; ii < 4; ++ii)
        #pragma unroll
        for (int dd = 0; dd < 8; ++dd) acc2p[ii][dd] = 0ull;

    int buf = 0;                       // buffer index the NEXT compute reads from

    for (int hc = 0; hc < 8; ++hc) {   // H chunks of 128
        // GEMM1 accumulators as packed f32x2 pairs: (even-k partial, odd-k partial)
        unsigned long long acc1p[4][4];
        #pragma unroll
        for (int ii = 0; ii < 4; ++ii)
            #pragma unroll
            for (int jj = 0; jj < 4; ++jj) acc1p[ii][jj] = 0ull;

        // ---- GEMM1: h[32x128] = xs[32x256] * W1chunk^T  (FFMA2, 64-wide slabs) ----
        // Next-slab staging split in two halves interleaved with the two
        // kk-compute halves; commit after the second half. Group membership and
        // the wait at the next step boundary are unchanged vs unsplit staging.
        // These per-step barriers also order the PREVIOUS chunk's GEMM2
        // hs-reads before this chunk's gelu hs-writes.
        for (int kt = 0; kt < 4; ++kt) {
            CP_WAIT0();
            __syncthreads();           // cur slab (+ xs on first iter) resident
            float* cur = buf ? U1 : U0;
            uint32_t nu = buf ? u0 : u1;
            if (kt < 3) stage_w1_half(nu, W1e, hc, kt + 1, tid, 0);
            else        stage_w2_half(nu, W2e, hc, 0, tid, 0);

            #pragma unroll
            for (int kh = 0; kh < 2; ++kh) {
                #pragma unroll
                for (int k2 = 0; k2 < 8; ++k2) {
                    int kk = kh * 8 + k2;
                    int blkA = kt * 16 + ((kk & 8) | ((kk ^ tt) & 7));
                    int blkB = (kk & 8) | ((kk ^ keyW1) & 7);       // hoisted key
                    // 16B loads viewed as two packed f32x2 operands each.
                    double2 a2[4], b2[4];
                    #pragma unroll
                    for (int ii = 0; ii < 4; ++ii) {
                        int r = tt * 4 + ii;
                        a2[ii] = *(const double2*)(xs + r * 256 + blkA * 4);
                    }
                    #pragma unroll
                    for (int dd = 0; dd < 4; ++dd) {
                        int j = th * 4 + dd;
                        b2[dd] = *(const double2*)(cur + j * 64 + blkB * 4);
                    }
                    #pragma unroll
                    for (int ii = 0; ii < 4; ++ii) {
                        unsigned long long ax = __double_as_longlong(a2[ii].x);
                        unsigned long long ay = __double_as_longlong(a2[ii].y);
                        #pragma unroll
                        for (int dd = 0; dd < 4; ++dd) {
                            FMA_F32X2(acc1p[ii][dd], ax, __double_as_longlong(b2[dd].x));
                            FMA_F32X2(acc1p[ii][dd], ay, __double_as_longlong(b2[dd].y));
                        }
                    }
                }
                if (kh == 0) {         // second staging half between compute halves
                    if (kt < 3) stage_w1_half(nu, W1e, hc, kt + 1, tid, 1);
                    else        stage_w2_half(nu, W2e, hc, 0, tid, 1);
                    CP_COMMIT();
                }
            }
            buf ^= 1;
        }

        // ---- fold pairs + gelu + store h tile (swizzled) ----
        // WAR safety vs the previous chunk's GEMM2 hs-reads: every thread
        // passed the 4 GEMM1 step barriers above AFTER finishing those reads,
        // so these writes cannot overtake them.
        #pragma unroll
        for (int ii = 0; ii < 4; ++ii) {
            int r = tt * 4 + ii;
            float4 g;
            float f[4];
            #pragma unroll
            for (int dd = 0; dd < 4; ++dd) {
                unsigned int lo, hi;
                asm("mov.b64 {%0, %1}, %2;" : "=r"(lo), "=r"(hi) : "l"(acc1p[ii][dd]));
                f[dd] = __uint_as_float(lo) + __uint_as_float(hi);
            }
            g.x = gelu_exact(f[0]);
            g.y = gelu_exact(f[1]);
            g.z = gelu_exact(f[2]);
            g.w = gelu_exact(f[3]);
            *(float4*)(hs + r * 128 + ((th & ~7) | ((th ^ tt) & 7)) * 4) = g;
        }

        // ---- GEMM2: out[32x256] += h[32x128] * W2chunk^T  (FFMA2, 64-wide slabs) ----
        for (int hk = 0; hk < 2; ++hk) {
            CP_WAIT0();
            __syncthreads();           // cur slab + hs stores resident; prev compute done
            float* cur = buf ? U1 : U0;
            uint32_t nu = buf ? u0 : u1;
            int has_next = (hk < 1) || (hc < 7);
            if (hk < 1)      stage_w2_half(nu, W2e, hc, 1, tid, 0);
            else if (hc < 7) stage_w1_half(nu, W1e, hc + 1, 0, tid, 0);

            #pragma unroll
            for (int kh = 0; kh < 2; ++kh) {
                #pragma unroll
                for (int k2 = 0; k2 < 8; ++k2) {
                    int kk = kh * 8 + k2;
                    int blkA = hk * 16 + ((kk & 8) | ((kk ^ tt) & 7));
                    // a = h[r][4 consecutive hh] as two f32x2 pairs
                    double2 a2[4];
                    #pragma unroll
                    for (int ii = 0; ii < 4; ++ii) {
                        int r = tt * 4 + ii;
                        a2[ii] = *(const double2*)(hs + r * 128 + blkA * 4);
                    }
                    #pragma unroll
                    for (int half = 0; half < 2; ++half) {
                        // U(W2) read key: (d>>2)&7 with d = th*8+half*4+dd ->
                        // (th*2+half)&7, invariant across dd — hoisted.
                        int blkB = (kk & 8) | ((kk ^ ((th * 2 + half) & 7)) & 7);
                        double2 b2[4];
                        #pragma unroll
                        for (int dd = 0; dd < 4; ++dd) {
                            int d = th * 8 + half * 4 + dd;
                            b2[dd] = *(const double2*)(cur + d * 64 + blkB * 4);
                        }
                        #pragma unroll
                        for (int ii = 0; ii < 4; ++ii) {
                            unsigned long long ax = __double_as_longlong(a2[ii].x);
                            unsigned long long ay = __double_as_longlong(a2[ii].y);
                            #pragma unroll
                            for (int dd = 0; dd < 4; ++dd) {
                                FMA_F32X2(acc2p[ii][half * 4 + dd], ax, __double_as_longlong(b2[dd].x));
                                FMA_F32X2(acc2p[ii][half * 4 + dd], ay, __double_as_longlong(b2[dd].y));
                            }
                        }
                    }
                }
                if (kh == 0) {         // second staging half between compute halves
                    if (has_next) {
                        if (hk < 1) stage_w2_half(nu, W2e, hc, 1, tid, 1);
                        else        stage_w1_half(nu, W1e, hc + 1, 0, tid, 1);
                    }
                    CP_COMMIT();       // empty group on the very last step: legal no-op
                }
            }
            buf ^= 1;
        }
        // (no end-of-chunk barrier: the next chunk's GEMM1 step barriers
        //  already order GEMM2 hs-reads before gelu hs-writes; after the
        //  final chunk only registers + s_tok/s_p are read.)
    }

    // epilogue: fold (even,odd) partials, scale, then 2 vector reductions per
    // thread-row; exactly 2 commutative adds per output element across all
    // blocks onto a zeroed base -> deterministic
    #pragma unroll
    for (int ii = 0; ii < 4; ++ii) {
        int r = tt * 4 + ii;
        int t = s_tok[r];
        if (t < 0) continue;
        float p = s_p[r];
        float v[8];
        #pragma unroll
        for (int dd = 0; dd < 8; ++dd) {
            unsigned int lo, hi;
            asm("mov.b64 {%0, %1}, %2;" : "=r"(lo), "=r"(hi) : "l"(acc2p[ii][dd]));
            v[dd] = p * (__uint_as_float(lo) + __uint_as_float(hi));
        }
        float* op = out + (size_t)t * D_DIM + th * 8;
        asm volatile("red.global.add.v4.f32 [%0], {%1, %2, %3, %4};\n"
                     :: "l"(op), "f"(v[0]), "f"(v[1]), "f"(v[2]), "f"(v[3])
                     : "memory");
        asm volatile("red.global.add.v4.f32 [%0], {%1, %2, %3, %4};\n"
                     :: "l"(op + 4), "f"(v[4]), "f"(v[5]), "f"(v[6]), "f"(v[7])
                     : "memory");
    }
}

// ---------------- aux loss ----------------
__global__ void aux_kernel(float* __restrict__ out, int out_size) {
    if (threadIdx.x == 0 && out_size > N_TOK * D_DIM) {
        float s = 0.f;
        #pragma unroll
        for (int e = 0; e < N_EXP; ++e) {
            float m = g_probsum[e] * (1.f / (float)N_TOK) - 1.f / (float)N_EXP;
            s += m * m;
        }
        out[N_TOK * D_DIM] = 0.01f * s * (1.f / (float)N_EXP);
    }
}

// ---------------- launch ----------------
extern "C" void kernel_launch(void* const* d_in, const int* in_sizes, int n_in,
                              void* d_out, int out_size) {
    const float* x  = (const float*)d_in[0];
    const float* W1 = (const float*)d_in[1];
    const float* W2 = (const float*)d_in[2];
    const float* rw = (const float*)d_in[3];
    const float* tg = (const float*)d_in[4];
    float* out = (float*)d_out;

    size_t smem_bytes = SMEM_FLOATS * sizeof(float);   // 180224
    cudaFuncSetAttribute(ffn_kernel, cudaFuncAttributeMaxDynamicSharedMemorySize,
                         (int)smem_bytes);

    init_kernel<<<4096, 256>>>(out);
    router_kernel<<<N_TOK / 256, 256>>>(x, rw, tg);
    ffn_kernel<<<MAX_TILES, 256, smem_bytes>>>(x, W1, W2, out);
    aux_kernel<<<1, 32>>>(out, out_size);
}

// round 17
// speedup vs baseline: 1.6801x; 1.6801x over previous
#include <cuda_runtime.h>
#include <stdint.h>
#include <math.h>

#define N_TOK 16384
#define D_DIM 256
#define H_DIM 1024
#define N_EXP 8
#define MT    32
#define MAX_TILES (2 * N_TOK / MT + N_EXP)

// ---------------- device-global scratch ----------------
__device__ int   g_count[N_EXP];
__device__ float g_probsum[N_EXP];
__device__ int   g_tok[N_EXP * N_TOK];
__device__ float g_p  [N_EXP * N_TOK];

// ---------------- cp.async helpers ----------------
#define CP_ASYNC16(dst_u32, src_ptr) \
    asm volatile("cp.async.cg.shared.global [%0], [%1], 16;\n" :: "r"(dst_u32), "l"(src_ptr))
#define CP_COMMIT() asm volatile("cp.async.commit_group;\n" ::: "memory")
#define CP_WAIT0()  asm volatile("cp.async.wait_group 0;\n"  ::: "memory")

__device__ __forceinline__ uint32_t to_tf32(float f) {
    uint32_t r;
    asm("cvt.rna.tf32.f32 %0, %1;" : "=r"(r) : "f"(f));
    return r;
}

// D += A(16x8 tf32, row) * B(8x8 tf32, col)
#define MMA_TF32(d0,d1,d2,d3,a0,a1,a2,a3,b0,b1) \
    asm volatile("mma.sync.aligned.m16n8k8.row.col.f32.tf32.tf32.f32 " \
                 "{%0,%1,%2,%3},{%4,%5,%6,%7},{%8,%9},{%0,%1,%2,%3};" \
                 : "+f"(d0), "+f"(d1), "+f"(d2), "+f"(d3) \
                 : "r"(a0), "r"(a1), "r"(a2), "r"(a3), "r"(b0), "r"(b1))

// ---------------- init ----------------
__global__ void init_kernel(float* __restrict__ out) {
    int i = blockIdx.x * blockDim.x + threadIdx.x;
    ((float4*)out)[i] = make_float4(0.f, 0.f, 0.f, 0.f);
    if (blockIdx.x == 0 && threadIdx.x < N_EXP) {
        g_count[threadIdx.x]   = 0;
        g_probsum[threadIdx.x] = 0.f;
    }
}

// ---------------- router (unchanged, measured correct) ----------------
__global__ void router_kernel(const float* __restrict__ x,
                              const float* __restrict__ rw,
                              const float* __restrict__ tg) {
    __shared__ float s_rw[3 * D_DIM];
    __shared__ float s_tg[N_EXP * 3];
    __shared__ float s_ps[N_EXP];
    int tid = threadIdx.x;
    for (int i = tid; i < 3 * D_DIM; i += 256) s_rw[i] = rw[i];
    if (tid < N_EXP * 3) s_tg[tid] = tg[tid];
    if (tid < N_EXP)     s_ps[tid] = 0.f;
    __syncthreads();

    int tok = blockIdx.x * 256 + tid;
    const float4* xr = (const float4*)(x + (size_t)tok * D_DIM);
    float z0 = 0.f, z1 = 0.f, z2 = 0.f;
    #pragma unroll 8
    for (int k4 = 0; k4 < 64; ++k4) {
        float4 v = xr[k4];
        int k = k4 * 4;
        z0 = fmaf(v.x, s_rw[k + 0], z0); z0 = fmaf(v.y, s_rw[k + 1], z0);
        z0 = fmaf(v.z, s_rw[k + 2], z0); z0 = fmaf(v.w, s_rw[k + 3], z0);
        z1 = fmaf(v.x, s_rw[256 + k + 0], z1); z1 = fmaf(v.y, s_rw[256 + k + 1], z1);
        z1 = fmaf(v.z, s_rw[256 + k + 2], z1); z1 = fmaf(v.w, s_rw[256 + k + 3], z1);
        z2 = fmaf(v.x, s_rw[512 + k + 0], z2); z2 = fmaf(v.y, s_rw[512 + k + 1], z2);
        z2 = fmaf(v.z, s_rw[512 + k + 2], z2); z2 = fmaf(v.w, s_rw[512 + k + 3], z2);
    }

    float p[N_EXP];
    float m = -1e30f;
    #pragma unroll
    for (int e = 0; e < N_EXP; ++e) {
        float l = z0 * s_tg[e * 3 + 0] + z1 * s_tg[e * 3 + 1] + z2 * s_tg[e * 3 + 2];
        p[e] = l;
        m = fmaxf(m, l);
    }
    float sum = 0.f;
    #pragma unroll
    for (int e = 0; e < N_EXP; ++e) { p[e] = expf(p[e] - m); sum += p[e]; }
    float inv = 1.f / sum;
    #pragma unroll
    for (int e = 0; e < N_EXP; ++e) p[e] *= inv;

    #pragma unroll
    for (int e = 0; e < N_EXP; ++e) atomicAdd(&s_ps[e], p[e]);

    int i0 = 0;
    #pragma unroll
    for (int e = 1; e < N_EXP; ++e) if (p[e] > p[i0]) i0 = e;
    int i1 = -1;
    #pragma unroll
    for (int e = 0; e < N_EXP; ++e) {
        if (e == i0) continue;
        if (i1 < 0 || p[e] > p[i1]) i1 = e;
    }
    float pn = p[i0] + p[i1] + 1e-8f;
    float q0 = p[i0] / pn, q1 = p[i1] / pn;

    int s0 = atomicAdd(&g_count[i0], 1);
    g_tok[i0 * N_TOK + s0] = tok;  g_p[i0 * N_TOK + s0] = q0;
    int s1 = atomicAdd(&g_count[i1], 1);
    g_tok[i1 * N_TOK + s1] = tok;  g_p[i1 * N_TOK + s1] = q1;

    __syncthreads();
    if (tid < N_EXP) atomicAdd(&g_probsum[tid], s_ps[tid]);
}

// ---------------- fused sparse FFN via mma.sync tf32 ----------------
__device__ __forceinline__ float gelu_exact(float v) {
    return 0.5f * v * (1.f + erff(v * 0.70710678118654752440f));
}

// padded strides (= 4 mod 32 -> fragment loads hit 32 distinct banks)
#define XS_STRIDE 260
#define HS_STRIDE 132
#define U_STRIDE  68
#define XS_FLOATS (32 * XS_STRIDE)            // 8320
#define HS_FLOATS (32 * HS_STRIDE)            // 4224
#define U_FLOATS  (256 * U_STRIDE)            // 17408 (W2 slab; W1 uses 128 rows)
#define SMEM_FLOATS (XS_FLOATS + HS_FLOATS + 2 * U_FLOATS)  // 47360 -> 189440 B

// Stage W1 slab: 128 rows(h) x 64 floats(k) -> U[row][U_STRIDE]
__device__ __forceinline__ void stage_w1(uint32_t u, const float* __restrict__ W1e,
                                         int hc, int kt, int tid) {
    #pragma unroll
    for (int pass = 0; pass < 8; ++pass) {
        int q = pass * 256 + tid;
        int j = q >> 4, kk = q & 15;
        const float* src = W1e + (size_t)(hc * 128 + j) * D_DIM + kt * 64 + kk * 4;
        uint32_t dst = u + (uint32_t)(j * U_STRIDE + kk * 4) * 4u;
        CP_ASYNC16(dst, src);
    }
}

// Stage W2 slab: 256 rows(d) x 64 floats(h) -> U[row][U_STRIDE]
__device__ __forceinline__ void stage_w2(uint32_t u, const float* __restrict__ W2e,
                                         int hc, int hk, int tid) {
    #pragma unroll
    for (int pass = 0; pass < 16; ++pass) {
        int q = pass * 256 + tid;
        int d = q >> 4, hh = q & 15;
        const float* src = W2e + (size_t)d * H_DIM + hc * 128 + hk * 64 + hh * 4;
        uint32_t dst = u + (uint32_t)(d * U_STRIDE + hh * 4) * 4u;
        CP_ASYNC16(dst, src);
    }
}

__global__ void __launch_bounds__(256)
ffn_kernel(const float* __restrict__ x, const float* __restrict__ W1,
           const float* __restrict__ W2, float* __restrict__ out) {
    // dense work map (measured correct)
    int bid = blockIdx.x;
    int e = 0, tile = 0, cnt = 0;
    {
        int base = 0, found = 0;
        #pragma unroll
        for (int ee = 0; ee < N_EXP; ++ee) {
            int c  = g_count[ee];
            int nt = (c + MT - 1) / MT;
            if (!found && bid < base + nt) {
                e = ee; tile = bid - base; cnt = c; found = 1;
            }
            base += nt;
        }
        if (!found) return;
    }
    int m0 = tile * MT;

    extern __shared__ float sm[];
    float* xs = sm;                           // [32][260]
    float* hs = sm + XS_FLOATS;               // [32][132]
    float* U0 = sm + XS_FLOATS + HS_FLOATS;   // [256][68]
    float* U1 = U0 + U_FLOATS;
    uint32_t xsu = (uint32_t)__cvta_generic_to_shared(xs);
    uint32_t u0  = (uint32_t)__cvta_generic_to_shared(U0);
    uint32_t u1  = (uint32_t)__cvta_generic_to_shared(U1);
    __shared__ int   s_tok[MT];
    __shared__ float s_p[MT];

    int tid  = threadIdx.x;
    int w    = tid >> 5;
    int lane = tid & 31;
    int g    = lane >> 2;        // fragment group 0..7
    int tig  = lane & 3;         // thread-in-group 0..3

    const float* W1e = W1 + (size_t)e * H_DIM * D_DIM;
    const float* W2e = W2 + (size_t)e * D_DIM * H_DIM;

    if (tid < MT) {
        int idx = m0 + tid;
        if (idx < cnt) { s_tok[tid] = g_tok[e * N_TOK + idx]; s_p[tid] = g_p[e * N_TOK + idx]; }
        else           { s_tok[tid] = -1;                     s_p[tid] = 0.f; }
    }
    __syncthreads();

    // async prologue: x gather (padded layout) + first W1 slab, one group
    #pragma unroll
    for (int pass = 0; pass < 8; ++pass) {
        int q = pass * 256 + tid;
        int row = q >> 6, c4 = q & 63;
        int t = s_tok[row]; if (t < 0) t = 0;
        const float* src = x + (size_t)t * D_DIM + c4 * 4;
        CP_ASYNC16(xsu + (uint32_t)(row * XS_STRIDE + c4 * 4) * 4u, src);
    }
    stage_w1(u0, W1e, 0, 0, tid);
    CP_COMMIT();

    // warp tiling: mtile = w&1 (16 rows), GEMM1 n-range (w>>1)*32, GEMM2 (w>>1)*64
    int arow = (w & 1) * 16 + g;
    int nb1  = (w >> 1) * 32;
    int nb2  = (w >> 1) * 64;

    float acc2[8][4];
    #pragma unroll
    for (int nt = 0; nt < 8; ++nt)
        #pragma unroll
        for (int c = 0; c < 4; ++c) acc2[nt][c] = 0.f;

    int buf = 0;

    for (int hc = 0; hc < 8; ++hc) {
        float acc1[4][4];
        #pragma unroll
        for (int nt = 0; nt < 4; ++nt)
            #pragma unroll
            for (int c = 0; c < 4; ++c) acc1[nt][c] = 0.f;

        // ---- GEMM1: h[32x128] = x[32x256] @ W1chunk^T ----
        for (int kt = 0; kt < 4; ++kt) {
            CP_WAIT0();
            __syncthreads();
            float* cur = buf ? U1 : U0;
            uint32_t nu = buf ? u0 : u1;
            if (kt < 3) stage_w1(nu, W1e, hc, kt + 1, tid);
            else        stage_w2(nu, W2e, hc, 0, tid);
            CP_COMMIT();

            #pragma unroll
            for (int ks = 0; ks < 8; ++ks) {
                int kc = kt * 64 + ks * 8 + tig;
                uint32_t A0 = to_tf32(xs[arow * XS_STRIDE + kc]);
                uint32_t A1 = to_tf32(xs[(arow + 8) * XS_STRIDE + kc]);
                uint32_t A2 = to_tf32(xs[arow * XS_STRIDE + kc + 4]);
                uint32_t A3 = to_tf32(xs[(arow + 8) * XS_STRIDE + kc + 4]);
                #pragma unroll
                for (int nt = 0; nt < 4; ++nt) {
                    int brow = nb1 + nt * 8 + g;
                    uint32_t B0 = to_tf32(cur[brow * U_STRIDE + ks * 8 + tig]);
                    uint32_t B1 = to_tf32(cur[brow * U_STRIDE + ks * 8 + tig + 4]);
                    MMA_TF32(acc1[nt][0], acc1[nt][1], acc1[nt][2], acc1[nt][3],
                             A0, A1, A2, A3, B0, B1);
                }
            }
            buf ^= 1;
        }

        // ---- gelu + store h tile ----
        // D layout: c0:(g, 2tig) c1:(g, 2tig+1) c2:(g+8, 2tig) c3:(g+8, 2tig+1)
        #pragma unroll
        for (int nt = 0; nt < 4; ++nt) {
            int colb = nb1 + nt * 8 + 2 * tig;
            hs[arow * HS_STRIDE + colb]           = gelu_exact(acc1[nt][0]);
            hs[arow * HS_STRIDE + colb + 1]       = gelu_exact(acc1[nt][1]);
            hs[(arow + 8) * HS_STRIDE + colb]     = gelu_exact(acc1[nt][2]);
            hs[(arow + 8) * HS_STRIDE + colb + 1] = gelu_exact(acc1[nt][3]);
        }

        // ---- GEMM2: out[32x256] += h[32x128] @ W2chunk^T ----
        for (int hk = 0; hk < 2; ++hk) {
            CP_WAIT0();
            __syncthreads();          // W2 slab + hs stores visible
            float* cur = buf ? U1 : U0;
            uint32_t nu = buf ? u0 : u1;
            if (hk < 1)      stage_w2(nu, W2e, hc, 1, tid);
            else if (hc < 7) stage_w1(nu, W1e, hc + 1, 0, tid);
            CP_COMMIT();

            #pragma unroll
            for (int ks = 0; ks < 8; ++ks) {
                int kc = hk * 64 + ks * 8 + tig;
                uint32_t A0 = to_tf32(hs[arow * HS_STRIDE + kc]);
                uint32_t A1 = to_tf32(hs[(arow + 8) * HS_STRIDE + kc]);
                uint32_t A2 = to_tf32(hs[arow * HS_STRIDE + kc + 4]);
                uint32_t A3 = to_tf32(hs[(arow + 8) * HS_STRIDE + kc + 4]);
                #pragma unroll
                for (int nt = 0; nt < 8; ++nt) {
                    int brow = nb2 + nt * 8 + g;
                    uint32_t B0 = to_tf32(cur[brow * U_STRIDE + ks * 8 + tig]);
                    uint32_t B1 = to_tf32(cur[brow * U_STRIDE + ks * 8 + tig + 4]);
                    MMA_TF32(acc2[nt][0], acc2[nt][1], acc2[nt][2], acc2[nt][3],
                             A0, A1, A2, A3, B0, B1);
                }
            }
            buf ^= 1;
        }
        // next hc's GEMM1 step barriers order this chunk's GEMM2 hs-reads
        // before the next gelu hs-writes (same argument as fp32 version)
    }

    // epilogue: rows arow / arow+8, cols nb2+nt*8+2tig+{0,1}; exactly 2
    // commutative adds per output element chip-wide onto zeroed base
    int t0 = s_tok[arow];
    int t1 = s_tok[arow + 8];
    float p0 = s_p[arow];
    float p1 = s_p[arow + 8];
    #pragma unroll
    for (int nt = 0; nt < 8; ++nt) {
        int col = nb2 + nt * 8 + 2 * tig;
        if (t0 >= 0) {
            float* op = out + (size_t)t0 * D_DIM + col;
            asm volatile("red.global.add.v2.f32 [%0], {%1, %2};\n"
                         :: "l"(op), "f"(p0 * acc2[nt][0]), "f"(p0 * acc2[nt][1])
                         : "memory");
        }
        if (t1 >= 0) {
            float* op = out + (size_t)t1 * D_DIM + col;
            asm volatile("red.global.add.v2.f32 [%0], {%1, %2};\n"
                         :: "l"(op), "f"(p1 * acc2[nt][2]), "f"(p1 * acc2[nt][3])
                         : "memory");
        }
    }
}

// ---------------- aux loss ----------------
__global__ void aux_kernel(float* __restrict__ out, int out_size) {
    if (threadIdx.x == 0 && out_size > N_TOK * D_DIM) {
        float s = 0.f;
        #pragma unroll
        for (int e = 0; e < N_EXP; ++e) {
            float m = g_probsum[e] * (1.f / (float)N_TOK) - 1.f / (float)N_EXP;
            s += m * m;
        }
        out[N_TOK * D_DIM] = 0.01f * s * (1.f / (float)N_EXP);
    }
}

// ---------------- launch ----------------
extern "C" void kernel_launch(void* const* d_in, const int* in_sizes, int n_in,
                              void* d_out, int out_size) {
    const float* x  = (const float*)d_in[0];
    const float* W1 = (const float*)d_in[1];
    const float* W2 = (const float*)d_in[2];
    const float* rw = (const float*)d_in[3];
    const float* tg = (const float*)d_in[4];
    float* out = (float*)d_out;

    size_t smem_bytes = SMEM_FLOATS * sizeof(float);   // 189440
    cudaFuncSetAttribute(ffn_kernel, cudaFuncAttributeMaxDynamicSharedMemorySize,
                         (int)smem_bytes);

    init_kernel<<<4096, 256>>>(out);
    router_kernel<<<N_TOK / 256, 256>>>(x, rw, tg);
    ffn_kernel<<<MAX_TILES, 256, smem_bytes>>>(x, W1, W2, out);
    aux_kernel<<<1, 32>>>(out, out_size);
}